// round 11
// baseline (speedup 1.0000x reference)
#include <cuda_runtime.h>
#include <cstdint>
#include <cstddef>

// Bihomogeneous_k3 — warp-per-row, fused re+im, phase-aligned re-stores
// (R6 memory pattern, byte-identical), plus c0-class specialization:
// rows are remapped so each grid-quarter has phase c0 in a fixed 8-wide
// band -> breakpoint windows shrink 63 -> 39 (fewer chain ops per group).
// R10 fix: dead trailing groups excluded via if-constexpr ELSE branch
// (previous version instantiated p_of(632), which does not terminate).

#define NVAR 5
#define NM 35
#define NPAIR 630
#define NCOL 1225
#define WPB 8
#define NGRP 20

__host__ __device__ constexpr int off_of(int p) { return p * (71 - p) / 2; }
__host__ __device__ constexpr int p_of(int s) {
    int p = 0;
    while (p < NM - 1 && off_of(p + 1) <= s) p++;   // clamped: safe for any s
    return p;
}
__host__ __device__ constexpr int cmin(int a, int b) { return a < b ? a : b; }

template<int... I> struct iseq {};
template<int N, int... I> struct make_iseq : make_iseq<N - 1, N - 1, I...> {};
template<int... I> struct make_iseq<0, I...> { using type = iseq<I...>; };

template<int PMIN, int... J>
__device__ __forceinline__ int p_from_s(int s, iseq<J...>) {
    int p = PMIN;
    ((p += (s >= off_of(PMIN + 1 + J)) ? 1 : 0), ...);
    return p;
}

// One 32-column group. Window of s values: [C0B+32G, C0B+32G+CW-1].
template<int G, int C0B, int CW>
__device__ __forceinline__ void do_group(const float2* __restrict__ zz,
                                         float* __restrict__ orow,
                                         float* __restrict__ orowi,
                                         int c0, int lane) {
    constexpr int SLO = C0B + 32 * G;
    if constexpr (SLO >= NPAIR) {
        return;                                     // dead group: nothing instantiated
    } else {
        const int s = c0 + 32 * G + lane;
        if constexpr (SLO + CW - 1 >= NPAIR) {
            if (s >= NPAIR) return;
        }
        constexpr int pmin = p_of(SLO);
        constexpr int pmax = p_of(cmin(SLO + CW - 1, NPAIR - 1));

        const int p = p_from_s<pmin>(s, typename make_iseq<pmax - pmin>::type{});
        const int q = s + p - ((p * (71 - p)) >> 1);    // s - off(p) + p

        const float2 a = zz[p];                         // broadcast: 1 wf
        const float2 b = zz[q];                         // consecutive q: 2 wf
        __stcs(orow + s, a.x * b.x + a.y * b.y);        // 128B-aligned: 1 wf
        if (q > p)
            __stcs(orowi + (s - p), a.y * b.x - a.x * b.y);
    }
}

template<int C0B, int CW, int... G>
__device__ __forceinline__ void all_groups(iseq<G...>, const float2* __restrict__ zz,
                                           float* __restrict__ orow,
                                           float* __restrict__ orowi,
                                           int c0, int lane) {
    (do_group<G, C0B, CW>(zz, orow, orowi, c0, lane), ...);
}

struct TabM { ushort ijk[40]; };
static constexpr TabM make_tabm() {
    TabM t{};
    int m = 0;
    for (int i = 0; i < NVAR; i++)
        for (int j = i; j < NVAR; j++)
            for (int k = j; k < NVAR; k++) {
                t.ijk[m] = (ushort)(i | (j << 4) | (k << 8));
                m++;
            }
    return t;
}
__device__ const TabM g_tabm = make_tabm();

// Shared per-row body: stages 0-2 up to the group loop.
struct RowCtx {
    const float2* zz;
    float* orow;
    float* orowi;
    int c0;
};

__device__ __forceinline__ void row_setup(int row, int warp, int lane,
                                          const float* __restrict__ z_re,
                                          const float* __restrict__ z_im,
                                          float* __restrict__ out,
                                          float2 (*szz)[NM + 1],
                                          float (*sz)[2][NVAR + 3],
                                          RowCtx& cx) {
    if (lane < NVAR) {
        sz[warp][0][lane] = z_re[row * NVAR + lane];
        sz[warp][1][lane] = z_im[row * NVAR + lane];
    }
    __syncwarp();
    for (int mm = lane; mm < NM; mm += 32) {
        const unsigned v = g_tabm.ijk[mm];
        const int i = v & 15, j = (v >> 4) & 15, k = (v >> 8) & 15;
        const float ar = sz[warp][0][i], ai = sz[warp][1][i];
        const float br = sz[warp][0][j], bi = sz[warp][1][j];
        const float cr = sz[warp][0][k], ci = sz[warp][1][k];
        const float tr = ar * br - ai * bi;
        const float ti = ar * bi + ai * br;
        szz[warp][mm] = make_float2(tr * cr - ti * ci, tr * ci + ti * cr);
    }
    __syncwarp();

    const int rowoff = row * NCOL;
    cx.c0    = (-rowoff) & 31;
    cx.orow  = out + (size_t)rowoff;
    cx.orowi = cx.orow + (NPAIR - 1);
    cx.zz    = szz[warp];

    // prologue: columns [0, c0): p = 0, q = s  (s < 31 < off(1) = 35)
    const int s0 = cx.c0 - 32 + lane;
    if (s0 >= 0) {
        const float2 a = cx.zz[0];
        const float2 b = cx.zz[s0];
        __stcs(cx.orow + s0, a.x * b.x + a.y * b.y);
        if (s0 > 0)
            __stcs(cx.orowi + s0, a.y * b.x - a.x * b.y);
    }
}

// ---- specialized kernel: 4 c0-classes, B % 128 == 0 ----
__global__ void __launch_bounds__(WPB * 32)
bihom_k3_kernel_spec(const float* __restrict__ z_re,
                     const float* __restrict__ z_im,
                     float* __restrict__ out, int B)
{
    __shared__ float2 szz[WPB][NM + 1];
    __shared__ float  sz[WPB][2][NVAR + 3];

    const int warp = threadIdx.x >> 5;
    const int lane = threadIdx.x & 31;
    const int wg   = blockIdx.x * WPB + warp;      // global warp id

    const int wpc = B >> 2;                        // warps per class
    const int k   = wg / wpc;                      // 0..3 (block-uniform: wpc % 8 == 0)
    const int rem = wg - k * wpc;
    const int j   = rem & 7;                       // c0 = 8k + j
    const int t   = rem >> 3;
    const int row = 32 * t + ((24 * k + 7 * j) & 31);   // c0(row) = (-(row*1225)) mod 32 = 8k+j

    RowCtx cx;
    row_setup(row, warp, lane, z_re, z_im, out, szz, sz, cx);

    // window width: lane(0..31) + j(0..7) => 39
    if (k == 0)
        all_groups<0, 39>(typename make_iseq<NGRP>::type{}, cx.zz, cx.orow, cx.orowi, cx.c0, lane);
    else if (k == 1)
        all_groups<8, 39>(typename make_iseq<NGRP>::type{}, cx.zz, cx.orow, cx.orowi, cx.c0, lane);
    else if (k == 2)
        all_groups<16, 39>(typename make_iseq<NGRP>::type{}, cx.zz, cx.orow, cx.orowi, cx.c0, lane);
    else
        all_groups<24, 39>(typename make_iseq<NGRP>::type{}, cx.zz, cx.orow, cx.orowi, cx.c0, lane);
}

// ---- generic fallback (R6): any B ----
__global__ void __launch_bounds__(WPB * 32)
bihom_k3_kernel_gen(const float* __restrict__ z_re,
                    const float* __restrict__ z_im,
                    float* __restrict__ out, int B)
{
    __shared__ float2 szz[WPB][NM + 1];
    __shared__ float  sz[WPB][2][NVAR + 3];

    const int warp = threadIdx.x >> 5;
    const int lane = threadIdx.x & 31;
    const int row  = blockIdx.x * WPB + warp;
    if (row >= B) return;

    RowCtx cx;
    row_setup(row, warp, lane, z_re, z_im, out, szz, sz, cx);
    all_groups<0, 63>(typename make_iseq<NGRP>::type{}, cx.zz, cx.orow, cx.orowi, cx.c0, lane);
}

extern "C" void kernel_launch(void* const* d_in, const int* in_sizes, int n_in,
                              void* d_out, int out_size) {
    const float* z_re = (const float*)d_in[0];
    const float* z_im = (const float*)d_in[1];
    float* out = (float*)d_out;
    const int B = in_sizes[0] / NVAR;

    if ((B & 127) == 0) {
        const int grid = B / WPB;                  // exact: B % (4*8*WPB-compatible) == 0
        bihom_k3_kernel_spec<<<grid, WPB * 32>>>(z_re, z_im, out, B);
    } else {
        const int grid = (B + WPB - 1) / WPB;
        bihom_k3_kernel_gen<<<grid, WPB * 32>>>(z_re, z_im, out, B);
    }
}

// round 12
// speedup vs baseline: 1.2775x; 1.2775x over previous
#include <cuda_runtime.h>
#include <cstdint>
#include <cstddef>

// Bihomogeneous_k3 — R6 memory pattern, byte- and order-identical
// (natural warp->row mapping, phase-aligned re-stores, fused re+im),
// with per-warp runtime dispatch into 4 c0-band specializations
// (window 63 -> 39) to shrink the breakpoint chains. Warp-uniform branch.

#define NVAR 5
#define NM 35
#define NPAIR 630
#define NCOL 1225
#define WPB 8
#define NGRP 20

__host__ __device__ constexpr int off_of(int p) { return p * (71 - p) / 2; }
__host__ __device__ constexpr int p_of(int s) {
    int p = 0;
    while (p < NM - 1 && off_of(p + 1) <= s) p++;   // clamped: safe for any s
    return p;
}
__host__ __device__ constexpr int cmin(int a, int b) { return a < b ? a : b; }

template<int... I> struct iseq {};
template<int N, int... I> struct make_iseq : make_iseq<N - 1, N - 1, I...> {};
template<int... I> struct make_iseq<0, I...> { using type = iseq<I...>; };

template<int PMIN, int... J>
__device__ __forceinline__ int p_from_s(int s, iseq<J...>) {
    int p = PMIN;
    ((p += (s >= off_of(PMIN + 1 + J)) ? 1 : 0), ...);
    return p;
}

// One 32-column group. s ranges over [C0B+32G, C0B+32G+CW-1].
template<int G, int C0B, int CW>
__device__ __forceinline__ void do_group(const float2* __restrict__ zz,
                                         float* __restrict__ orow,
                                         float* __restrict__ orowi,
                                         int c0, int lane) {
    constexpr int SLO = C0B + 32 * G;
    if constexpr (SLO >= NPAIR) {
        return;                                     // dead group
    } else {
        const int s = c0 + 32 * G + lane;
        if constexpr (SLO + CW - 1 >= NPAIR) {
            if (s >= NPAIR) return;
        }
        constexpr int pmin = p_of(SLO);
        constexpr int pmax = p_of(cmin(SLO + CW - 1, NPAIR - 1));

        const int p = p_from_s<pmin>(s, typename make_iseq<pmax - pmin>::type{});
        const int q = s + p - ((p * (71 - p)) >> 1);    // s - off(p) + p

        const float2 a = zz[p];                         // broadcast: 1 wf
        const float2 b = zz[q];                         // consecutive q: 2 wf
        __stcs(orow + s, a.x * b.x + a.y * b.y);        // 128B-aligned: 1 wf
        if (q > p)
            __stcs(orowi + (s - p), a.y * b.x - a.x * b.y);
    }
}

template<int C0B, int CW, int... G>
__device__ __forceinline__ void all_groups(iseq<G...>, const float2* __restrict__ zz,
                                           float* __restrict__ orow,
                                           float* __restrict__ orowi,
                                           int c0, int lane) {
    (do_group<G, C0B, CW>(zz, orow, orowi, c0, lane), ...);
}

struct TabM { ushort ijk[40]; };
static constexpr TabM make_tabm() {
    TabM t{};
    int m = 0;
    for (int i = 0; i < NVAR; i++)
        for (int j = i; j < NVAR; j++)
            for (int k = j; k < NVAR; k++) {
                t.ijk[m] = (ushort)(i | (j << 4) | (k << 8));
                m++;
            }
    return t;
}
__device__ const TabM g_tabm = make_tabm();

__global__ void __launch_bounds__(WPB * 32)
bihom_k3_kernel(const float* __restrict__ z_re,
                const float* __restrict__ z_im,
                float* __restrict__ out, int B)
{
    __shared__ float2 szz[WPB][NM + 1];
    __shared__ float  sz[WPB][2][NVAR + 3];

    const int warp = threadIdx.x >> 5;
    const int lane = threadIdx.x & 31;
    const int row  = blockIdx.x * WPB + warp;      // NATURAL mapping: row locality
    if (row >= B) return;

    // stage 0: row inputs into smem
    if (lane < NVAR) {
        sz[warp][0][lane] = z_re[row * NVAR + lane];
        sz[warp][1][lane] = z_im[row * NVAR + lane];
    }
    __syncwarp();

    // stage 1: 35 complex monomials z_i z_j z_k
    for (int mm = lane; mm < NM; mm += 32) {
        const unsigned v = g_tabm.ijk[mm];
        const int i = v & 15, j = (v >> 4) & 15, k = (v >> 8) & 15;
        const float ar = sz[warp][0][i], ai = sz[warp][1][i];
        const float br = sz[warp][0][j], bi = sz[warp][1][j];
        const float cr = sz[warp][0][k], ci = sz[warp][1][k];
        const float tr = ar * br - ai * bi;
        const float ti = ar * bi + ai * br;
        szz[warp][mm] = make_float2(tr * cr - ti * ci, tr * ci + ti * cr);
    }
    __syncwarp();

    // stage 2: phase so that (row*NCOL + c0) is 128B-aligned
    const int rowoff = row * NCOL;
    const int c0 = (-rowoff) & 31;

    float* __restrict__ orow  = out + (size_t)rowoff;
    float* __restrict__ orowi = orow + (NPAIR - 1);   // im col = 629 + s - p
    const float2* zz = szz[warp];

    // prologue: columns [0, c0). Here s < 31 < off(1)=35 -> p = 0, q = s.
    {
        const int s0 = c0 - 32 + lane;
        if (s0 >= 0) {
            const float2 a = zz[0];
            const float2 b = zz[s0];
            __stcs(orow + s0, a.x * b.x + a.y * b.y);
            if (s0 > 0)
                __stcs(orowi + s0, a.y * b.x - a.x * b.y);
        }
    }

    // per-warp dispatch on c0 band (warp-uniform branch, memory order unchanged)
    const int k = c0 >> 3;
    if (k == 0)
        all_groups<0, 39>(typename make_iseq<NGRP>::type{}, zz, orow, orowi, c0, lane);
    else if (k == 1)
        all_groups<8, 39>(typename make_iseq<NGRP>::type{}, zz, orow, orowi, c0, lane);
    else if (k == 2)
        all_groups<16, 39>(typename make_iseq<NGRP>::type{}, zz, orow, orowi, c0, lane);
    else
        all_groups<24, 39>(typename make_iseq<NGRP>::type{}, zz, orow, orowi, c0, lane);
}

extern "C" void kernel_launch(void* const* d_in, const int* in_sizes, int n_in,
                              void* d_out, int out_size) {
    const float* z_re = (const float*)d_in[0];
    const float* z_im = (const float*)d_in[1];
    float* out = (float*)d_out;
    const int B = in_sizes[0] / NVAR;
    const int grid = (B + WPB - 1) / WPB;
    bihom_k3_kernel<<<grid, WPB * 32>>>(z_re, z_im, out, B);
}